// round 2
// baseline (speedup 1.0000x reference)
#include <cuda_runtime.h>

#define NPIX 65536   // 256*256
#define NT   1024
#define KG   16      // NPIX/4/NT float4-groups per thread

__device__ double g_partials[1024];

struct Scratch {
    unsigned nred[32];
    unsigned sred[32];
    float    fmin[32];
    float    fmax[32];
    float    facc[32];
    int      qt;
    int      done;
    int      flip;
    unsigned border[4];
};

extern "C" __global__ void __launch_bounds__(NT, 1)
mask_loss_main(const float* __restrict__ hr, const float* __restrict__ sr, int B)
{
    extern __shared__ unsigned char smem[];
    unsigned short*     qs  = (unsigned short*)smem;
    unsigned long long* q64 = (unsigned long long*)smem;
    Scratch* sc = (Scratch*)(smem + NPIX * 2);

    const int tid  = threadIdx.x;
    const int lane = tid & 31;
    const int warp = tid >> 5;
    const int b    = blockIdx.x;

    // ---------------- Phase 1: gray + quantize into SMEM, min/max/sum ----------------
    const float4* p0 = (const float4*)(hr + (size_t)b * 3 * NPIX);
    const float4* p1 = p0 + NPIX / 4;
    const float4* p2 = p1 + NPIX / 4;

    float gmin = 3.0e38f, gmax = -3.0e38f;
    unsigned sq = 0;                       // per-thread sum of q (<= 64*65535, fits u32)
    const float inv3 = 1.0f / 3.0f;

    #pragma unroll
    for (int k = 0; k < KG; k++) {
        int idx = tid + (k << 10);
        float4 a = p0[idx], c = p1[idx], d = p2[idx];
        float x0 = (a.x + c.x + d.x) * inv3;
        float x1 = (a.y + c.y + d.y) * inv3;
        float x2 = (a.z + c.z + d.z) * inv3;
        float x3 = (a.w + c.w + d.w) * inv3;
        gmin = fminf(gmin, fminf(fminf(x0, x1), fminf(x2, x3)));
        gmax = fmaxf(gmax, fmaxf(fmaxf(x0, x1), fmaxf(x2, x3)));
        unsigned q0 = (unsigned)fminf(x0 * 65536.0f, 65535.0f);
        unsigned q1 = (unsigned)fminf(x1 * 65536.0f, 65535.0f);
        unsigned q2 = (unsigned)fminf(x2 * 65536.0f, 65535.0f);
        unsigned q3 = (unsigned)fminf(x3 * 65536.0f, 65535.0f);
        sq += q0 + q1 + q2 + q3;
        unsigned lo = q0 | (q1 << 16);
        unsigned hi = q2 | (q3 << 16);
        q64[idx] = ((unsigned long long)hi << 32) | (unsigned long long)lo;
    }

    #pragma unroll
    for (int o = 16; o; o >>= 1) {
        gmin = fminf(gmin, __shfl_xor_sync(~0u, gmin, o));
        gmax = fmaxf(gmax, __shfl_xor_sync(~0u, gmax, o));
        sq  += __shfl_xor_sync(~0u, sq, o);
    }
    if (lane == 0) { sc->fmin[warp] = gmin; sc->fmax[warp] = gmax; sc->nred[warp] = sq; }
    __syncthreads();

    double Stot = 0.0;   // valid only in (warp 0, lane 0)
    if (warp == 0) {
        float mn = sc->fmin[lane];
        float mx = sc->fmax[lane];
        unsigned long long s = (unsigned long long)sc->nred[lane];
        #pragma unroll
        for (int o = 16; o; o >>= 1) {
            mn = fminf(mn, __shfl_xor_sync(~0u, mn, o));
            mx = fmaxf(mx, __shfl_xor_sync(~0u, mx, o));
            s += __shfl_xor_sync(~0u, s, o);
        }
        if (lane == 0) {
            Stot = ((double)s + 32768.0) * (1.0 / 65536.0);
            float t = 0.5f * (mn + mx);                 // init c0=min, c1=max
            sc->qt   = (int)floorf(t * 65536.0f - 0.5f);
            sc->done = 0;
        }
    }
    __syncthreads();

    // ---------------- Phase 2: Lloyd iterations (integer threshold map) ----------------
    int qt = sc->qt;
    int prev = -0x70000000;  // thread-0-only history (tau_{i-1})

    for (int it = 0; it < 20; it++) {
        unsigned n = 0, s = 0;
        #pragma unroll
        for (int k = 0; k < KG; k++) {
            unsigned long long v = q64[tid + (k << 10)];
            int a0 = (int)((unsigned)v & 0xFFFFu);
            int a1 = (int)(((unsigned)v >> 16) & 0xFFFFu);
            int a2 = (int)((unsigned)(v >> 32) & 0xFFFFu);
            int a3 = (int)((unsigned)(v >> 48));
            if (a0 > qt) { n++; s += (unsigned)a0; }
            if (a1 > qt) { n++; s += (unsigned)a1; }
            if (a2 > qt) { n++; s += (unsigned)a2; }
            if (a3 > qt) { n++; s += (unsigned)a3; }
        }
        #pragma unroll
        for (int o = 16; o; o >>= 1) {
            n += __shfl_xor_sync(~0u, n, o);
            s += __shfl_xor_sync(~0u, s, o);
        }
        if (lane == 0) { sc->nred[warp] = n; sc->sred[warp] = s; }
        __syncthreads();

        if (warp == 0) {
            unsigned N1 = sc->nred[lane];
            unsigned long long S1 = (unsigned long long)sc->sred[lane];
            #pragma unroll
            for (int o = 16; o; o >>= 1) {
                N1 += __shfl_xor_sync(~0u, N1, o);
                S1 += __shfl_xor_sync(~0u, S1, o);
            }
            if (lane == 0) {
                float s1 = (float)(((double)S1 + 0.5 * (double)N1) * (1.0 / 65536.0));
                float s0 = (float)Stot - s1;
                unsigned N0 = (unsigned)NPIX - N1;
                float c1 = s1 / (float)max(N1, 1u);
                float c0 = s0 / (float)max(N0, 1u);
                float t  = 0.5f * (c0 + c1);
                int qn = (int)floorf(t * 65536.0f - 0.5f);
                if (qn == qt) {                      // fixed point: all further steps no-op
                    sc->qt = qn; sc->done = 1;
                } else if (qn == prev) {             // 2-cycle {prev, qt}; pick parity of tau_21
                    int m = 19 - it;                 // steps remaining after tau_{it+2}
                    sc->qt = ((m & 1) == 0) ? qn : qt;
                    sc->done = 1;
                } else {
                    prev = qt;
                    sc->qt = qn;
                }
            }
        }
        __syncthreads();
        qt = sc->qt;
        if (sc->done) break;
    }

    // ---------------- Phase 3a: border vote ----------------
    if (tid < 4) sc->border[tid] = 0;
    __syncthreads();
    {
        const int g = tid >> 8;          // 0:row0 1:row255 2:col0 3:col255 (warp-uniform)
        const int j = tid & 255;
        int qv;
        if      (g == 0) qv = (int)qs[j];
        else if (g == 1) qv = (int)qs[65280 + j];
        else if (g == 2) qv = (int)qs[j << 8];
        else             qv = (int)qs[(j << 8) + 255];
        unsigned c = (qv > qt) ? 1u : 0u;
        #pragma unroll
        for (int o = 16; o; o >>= 1) c += __shfl_xor_sync(~0u, c, o);
        if (lane == 0) atomicAdd(&sc->border[g], c);
    }
    __syncthreads();
    if (tid == 0) {
        int num = (sc->border[0] > 128u) + (sc->border[1] > 128u)
                + (sc->border[2] > 128u) + (sc->border[3] > 128u);
        sc->flip = (num >= 3) ? 1 : 0;
    }
    __syncthreads();
    const int flip = sc->flip;

    // ---------------- Phase 3b: loss vs sr_mask ----------------
    const float4* sp = (const float4*)(sr + (size_t)b * NPIX);
    float acc = 0.0f;
    #pragma unroll
    for (int k = 0; k < KG; k++) {
        int idx = tid + (k << 10);
        unsigned long long v = q64[idx];
        float4 sv = sp[idx];
        int m0 = (((int)((unsigned)v & 0xFFFFu))         > qt) ^ flip;
        int m1 = (((int)(((unsigned)v >> 16) & 0xFFFFu)) > qt) ^ flip;
        int m2 = (((int)((unsigned)(v >> 32) & 0xFFFFu)) > qt) ^ flip;
        int m3 = (((int)((unsigned)(v >> 48)))           > qt) ^ flip;
        float d0 = sv.x - (float)m0;
        float d1 = sv.y - (float)m1;
        float d2 = sv.z - (float)m2;
        float d3 = sv.w - (float)m3;
        acc += d0 * d0 + d1 * d1 + d2 * d2 + d3 * d3;
    }
    #pragma unroll
    for (int o = 16; o; o >>= 1) acc += __shfl_xor_sync(~0u, acc, o);
    if (lane == 0) sc->facc[warp] = acc;
    __syncthreads();
    if (warp == 0) {
        float a = sc->facc[lane];
        #pragma unroll
        for (int o = 16; o; o >>= 1) a += __shfl_xor_sync(~0u, a, o);
        if (lane == 0) g_partials[b] = (double)a;
    }
}

extern "C" __global__ void mask_loss_finalize(float* out, int B)
{
    double a = 0.0;
    for (int i = threadIdx.x; i < B; i += 32) a += g_partials[i];
    #pragma unroll
    for (int o = 16; o; o >>= 1) a += __shfl_xor_sync(~0u, a, o);
    if (threadIdx.x == 0) out[0] = (float)(a / ((double)B * (double)NPIX));
}

extern "C" void kernel_launch(void* const* d_in, const int* in_sizes, int n_in,
                              void* d_out, int out_size)
{
    const float* hr = (const float*)d_in[0];
    const float* sr = (const float*)d_in[1];
    int B = in_sizes[1] / NPIX;

    size_t smem = (size_t)NPIX * 2 + sizeof(Scratch);
    cudaFuncSetAttribute(mask_loss_main,
                         cudaFuncAttributeMaxDynamicSharedMemorySize, (int)smem);

    mask_loss_main<<<B, NT, smem>>>(hr, sr, B);
    mask_loss_finalize<<<1, 32>>>((float*)d_out, B);
}

// round 3
// speedup vs baseline: 1.0207x; 1.0207x over previous
#include <cuda_runtime.h>

#define NPIX 65536   // 256*256
#define NT   1024
#define KG   16      // NPIX/4/NT float4-groups per thread

__device__ double g_partials[1024];

struct Scratch {
    unsigned nred[32];
    unsigned sred[32];
    float    fmin[32];
    float    fmax[32];
    float    facc[32];
    int      qt;
    int      done;
    int      flip;
    unsigned border[4];
};

extern "C" __global__ void __launch_bounds__(NT, 1)
mask_loss_main(const float* __restrict__ hr, const float* __restrict__ sr, int B)
{
    extern __shared__ unsigned char smem[];
    unsigned short*     qs  = (unsigned short*)smem;
    unsigned long long* q64 = (unsigned long long*)smem;
    Scratch* sc = (Scratch*)(smem + NPIX * 2);

    const int tid  = threadIdx.x;
    const int lane = tid & 31;
    const int warp = tid >> 5;
    const int b    = blockIdx.x;

    // ---------------- Phase 1: gray + quantize into SMEM, min/max/sum ----------------
    const float4* p0 = (const float4*)(hr + (size_t)b * 3 * NPIX);
    const float4* p1 = p0 + NPIX / 4;
    const float4* p2 = p1 + NPIX / 4;

    float gmin = 3.0e38f, gmax = -3.0e38f;
    unsigned sq = 0;                       // per-thread sum of q (<= 64*65535, fits u32)
    const float inv3 = 1.0f / 3.0f;

    #pragma unroll
    for (int k = 0; k < KG; k++) {
        int idx = tid + (k << 10);
        float4 a = p0[idx], c = p1[idx], d = p2[idx];
        float x0 = (a.x + c.x + d.x) * inv3;
        float x1 = (a.y + c.y + d.y) * inv3;
        float x2 = (a.z + c.z + d.z) * inv3;
        float x3 = (a.w + c.w + d.w) * inv3;
        gmin = fminf(gmin, fminf(fminf(x0, x1), fminf(x2, x3)));
        gmax = fmaxf(gmax, fmaxf(fmaxf(x0, x1), fmaxf(x2, x3)));
        unsigned q0 = (unsigned)fminf(x0 * 65536.0f, 65535.0f);
        unsigned q1 = (unsigned)fminf(x1 * 65536.0f, 65535.0f);
        unsigned q2 = (unsigned)fminf(x2 * 65536.0f, 65535.0f);
        unsigned q3 = (unsigned)fminf(x3 * 65536.0f, 65535.0f);
        sq += q0 + q1 + q2 + q3;
        unsigned lo = q0 | (q1 << 16);
        unsigned hi = q2 | (q3 << 16);
        q64[idx] = ((unsigned long long)hi << 32) | (unsigned long long)lo;
    }

    #pragma unroll
    for (int o = 16; o; o >>= 1) {
        gmin = fminf(gmin, __shfl_xor_sync(~0u, gmin, o));
        gmax = fmaxf(gmax, __shfl_xor_sync(~0u, gmax, o));
        sq  += __shfl_xor_sync(~0u, sq, o);
    }
    if (lane == 0) { sc->fmin[warp] = gmin; sc->fmax[warp] = gmax; sc->nred[warp] = sq; }
    __syncthreads();

    double Stot = 0.0;   // valid only in (warp 0, lane 0)
    if (warp == 0) {
        float mn = sc->fmin[lane];
        float mx = sc->fmax[lane];
        unsigned long long s = (unsigned long long)sc->nred[lane];
        #pragma unroll
        for (int o = 16; o; o >>= 1) {
            mn = fminf(mn, __shfl_xor_sync(~0u, mn, o));
            mx = fmaxf(mx, __shfl_xor_sync(~0u, mx, o));
            s += __shfl_xor_sync(~0u, s, o);
        }
        if (lane == 0) {
            Stot = ((double)s + 32768.0) * (1.0 / 65536.0);
            float t = 0.5f * (mn + mx);                 // init c0=min, c1=max
            sc->qt   = (int)floorf(t * 65536.0f - 0.5f);
            sc->done = 0;
        }
    }
    __syncthreads();

    // ---------------- Phase 2: Lloyd iterations (integer threshold map) ----------------
    int qt = sc->qt;
    int prev = -0x70000000;  // thread-0-only history (tau_{i-1})

    for (int it = 0; it < 20; it++) {
        unsigned n = 0, s = 0;
        #pragma unroll
        for (int k = 0; k < KG; k++) {
            unsigned long long v = q64[tid + (k << 10)];
            int a0 = (int)((unsigned)v & 0xFFFFu);
            int a1 = (int)(((unsigned)v >> 16) & 0xFFFFu);
            int a2 = (int)((unsigned)(v >> 32) & 0xFFFFu);
            int a3 = (int)((unsigned)(v >> 48));
            if (a0 > qt) { n++; s += (unsigned)a0; }
            if (a1 > qt) { n++; s += (unsigned)a1; }
            if (a2 > qt) { n++; s += (unsigned)a2; }
            if (a3 > qt) { n++; s += (unsigned)a3; }
        }
        #pragma unroll
        for (int o = 16; o; o >>= 1) {
            n += __shfl_xor_sync(~0u, n, o);
            s += __shfl_xor_sync(~0u, s, o);
        }
        if (lane == 0) { sc->nred[warp] = n; sc->sred[warp] = s; }
        __syncthreads();

        if (warp == 0) {
            unsigned N1 = sc->nred[lane];
            unsigned long long S1 = (unsigned long long)sc->sred[lane];
            #pragma unroll
            for (int o = 16; o; o >>= 1) {
                N1 += __shfl_xor_sync(~0u, N1, o);
                S1 += __shfl_xor_sync(~0u, S1, o);
            }
            if (lane == 0) {
                float s1 = (float)(((double)S1 + 0.5 * (double)N1) * (1.0 / 65536.0));
                float s0 = (float)Stot - s1;
                unsigned N0 = (unsigned)NPIX - N1;
                float c1 = s1 / (float)max(N1, 1u);
                float c0 = s0 / (float)max(N0, 1u);
                float t  = 0.5f * (c0 + c1);
                int qn = (int)floorf(t * 65536.0f - 0.5f);
                if (qn == qt) {                      // fixed point: all further steps no-op
                    sc->qt = qn; sc->done = 1;
                } else if (qn == prev) {             // 2-cycle {prev, qt}; pick parity of tau_21
                    int m = 19 - it;                 // steps remaining after tau_{it+2}
                    sc->qt = ((m & 1) == 0) ? qn : qt;
                    sc->done = 1;
                } else {
                    prev = qt;
                    sc->qt = qn;
                }
            }
        }
        __syncthreads();
        qt = sc->qt;
        if (sc->done) break;
    }

    // ---------------- Phase 3a: border vote ----------------
    if (tid < 4) sc->border[tid] = 0;
    __syncthreads();
    {
        const int g = tid >> 8;          // 0:row0 1:row255 2:col0 3:col255 (warp-uniform)
        const int j = tid & 255;
        int qv;
        if      (g == 0) qv = (int)qs[j];
        else if (g == 1) qv = (int)qs[65280 + j];
        else if (g == 2) qv = (int)qs[j << 8];
        else             qv = (int)qs[(j << 8) + 255];
        unsigned c = (qv > qt) ? 1u : 0u;
        #pragma unroll
        for (int o = 16; o; o >>= 1) c += __shfl_xor_sync(~0u, c, o);
        if (lane == 0) atomicAdd(&sc->border[g], c);
    }
    __syncthreads();
    if (tid == 0) {
        int num = (sc->border[0] > 128u) + (sc->border[1] > 128u)
                + (sc->border[2] > 128u) + (sc->border[3] > 128u);
        sc->flip = (num >= 3) ? 1 : 0;
    }
    __syncthreads();
    const int flip = sc->flip;

    // ---------------- Phase 3b: loss vs sr_mask ----------------
    const float4* sp = (const float4*)(sr + (size_t)b * NPIX);
    float acc = 0.0f;
    #pragma unroll
    for (int k = 0; k < KG; k++) {
        int idx = tid + (k << 10);
        unsigned long long v = q64[idx];
        float4 sv = sp[idx];
        int m0 = (((int)((unsigned)v & 0xFFFFu))         > qt) ^ flip;
        int m1 = (((int)(((unsigned)v >> 16) & 0xFFFFu)) > qt) ^ flip;
        int m2 = (((int)((unsigned)(v >> 32) & 0xFFFFu)) > qt) ^ flip;
        int m3 = (((int)((unsigned)(v >> 48)))           > qt) ^ flip;
        float d0 = sv.x - (float)m0;
        float d1 = sv.y - (float)m1;
        float d2 = sv.z - (float)m2;
        float d3 = sv.w - (float)m3;
        acc += d0 * d0 + d1 * d1 + d2 * d2 + d3 * d3;
    }
    #pragma unroll
    for (int o = 16; o; o >>= 1) acc += __shfl_xor_sync(~0u, acc, o);
    if (lane == 0) sc->facc[warp] = acc;
    __syncthreads();
    if (warp == 0) {
        float a = sc->facc[lane];
        #pragma unroll
        for (int o = 16; o; o >>= 1) a += __shfl_xor_sync(~0u, a, o);
        if (lane == 0) g_partials[b] = (double)a;
    }
}

extern "C" __global__ void mask_loss_finalize(float* out, int B)
{
    double a = 0.0;
    for (int i = threadIdx.x; i < B; i += 32) a += g_partials[i];
    #pragma unroll
    for (int o = 16; o; o >>= 1) a += __shfl_xor_sync(~0u, a, o);
    if (threadIdx.x == 0) out[0] = (float)(a / ((double)B * (double)NPIX));
}

extern "C" void kernel_launch(void* const* d_in, const int* in_sizes, int n_in,
                              void* d_out, int out_size)
{
    const float* hr = (const float*)d_in[0];
    const float* sr = (const float*)d_in[1];
    int B = in_sizes[1] / NPIX;

    size_t smem = (size_t)NPIX * 2 + sizeof(Scratch);
    cudaFuncSetAttribute(mask_loss_main,
                         cudaFuncAttributeMaxDynamicSharedMemorySize, (int)smem);

    mask_loss_main<<<B, NT, smem>>>(hr, sr, B);
    mask_loss_finalize<<<1, 32>>>((float*)d_out, B);
}

// round 4
// speedup vs baseline: 1.0488x; 1.0275x over previous
#include <cuda_runtime.h>

#define NPIX 65536   // 256*256
#define NT   512
#define KG   32      // NPIX/4/NT float4-groups per thread
#define KS   16      // NPIX/8/NT uint4 (8 x u16) groups per thread

__device__ double   g_partials[1024];
__device__ unsigned g_count = 0;

struct Scratch {
    unsigned nred[16];
    unsigned sred[16];
    float    fmin[16];
    float    fmax[16];
    float    facc[16];
    int      qt;
    int      done;
    int      flip;
    unsigned border[4];
};

extern "C" __global__ void __launch_bounds__(NT, 1)
mask_loss_main(const float* __restrict__ hr, const float* __restrict__ sr,
               float* __restrict__ out, int B)
{
    extern __shared__ unsigned char smem[];
    unsigned short*     qs   = (unsigned short*)smem;
    unsigned long long* q64  = (unsigned long long*)smem;
    uint4*              q128 = (uint4*)smem;
    Scratch* sc = (Scratch*)(smem + NPIX * 2);

    const int tid  = threadIdx.x;
    const int lane = tid & 31;
    const int warp = tid >> 5;
    const int b    = blockIdx.x;

    // ---------------- Phase 1: gray + quantize into SMEM, min/max/sum ----------------
    const float4* p0 = (const float4*)(hr + (size_t)b * 3 * NPIX);
    const float4* p1 = p0 + NPIX / 4;
    const float4* p2 = p1 + NPIX / 4;

    float gmin = 3.0e38f, gmax = -3.0e38f;
    unsigned long long sq = 0;
    const float inv3 = 1.0f / 3.0f;

    #pragma unroll
    for (int k = 0; k < KG; k++) {
        int idx = tid + k * NT;
        float4 a = p0[idx], c = p1[idx], d = p2[idx];
        float x0 = (a.x + c.x + d.x) * inv3;
        float x1 = (a.y + c.y + d.y) * inv3;
        float x2 = (a.z + c.z + d.z) * inv3;
        float x3 = (a.w + c.w + d.w) * inv3;
        gmin = fminf(gmin, fminf(fminf(x0, x1), fminf(x2, x3)));
        gmax = fmaxf(gmax, fmaxf(fmaxf(x0, x1), fmaxf(x2, x3)));
        unsigned q0 = (unsigned)fminf(x0 * 65536.0f, 65535.0f);
        unsigned q1 = (unsigned)fminf(x1 * 65536.0f, 65535.0f);
        unsigned q2 = (unsigned)fminf(x2 * 65536.0f, 65535.0f);
        unsigned q3 = (unsigned)fminf(x3 * 65536.0f, 65535.0f);
        sq += (unsigned long long)(q0 + q1 + q2 + q3);
        unsigned lo = q0 | (q1 << 16);
        unsigned hi = q2 | (q3 << 16);
        q64[idx] = ((unsigned long long)hi << 32) | (unsigned long long)lo;
    }

    #pragma unroll
    for (int o = 16; o; o >>= 1) {
        gmin = fminf(gmin, __shfl_xor_sync(~0u, gmin, o));
        gmax = fmaxf(gmax, __shfl_xor_sync(~0u, gmax, o));
        sq  += __shfl_xor_sync(~0u, sq, o);
    }
    if (lane == 0) {
        sc->fmin[warp] = gmin; sc->fmax[warp] = gmax;
        sc->nred[warp] = (unsigned)(sq & 0xFFFFFFFFull);
        sc->sred[warp] = (unsigned)(sq >> 32);
    }
    __syncthreads();

    double Stot = 0.0;   // valid only in (warp 0, lane 0)
    if (warp == 0 && lane < 16) {
        float mn = sc->fmin[lane];
        float mx = sc->fmax[lane];
        unsigned long long s = ((unsigned long long)sc->sred[lane] << 32)
                             | (unsigned long long)sc->nred[lane];
        #pragma unroll
        for (int o = 8; o; o >>= 1) {
            mn = fminf(mn, __shfl_xor_sync(0xFFFFu, mn, o));
            mx = fmaxf(mx, __shfl_xor_sync(0xFFFFu, mx, o));
            s += __shfl_xor_sync(0xFFFFu, s, o);
        }
        if (lane == 0) {
            Stot = ((double)s + 32768.0) * (1.0 / 65536.0);
            float t = 0.5f * (mn + mx);                 // init c0=min, c1=max
            sc->qt   = (int)floorf(t * 65536.0f - 0.5f);
            sc->done = 0;
        }
    }
    __syncthreads();

    // ---------------- Phase 2: Lloyd iterations (integer threshold map) ----------------
    int qt = sc->qt;
    int prev = -0x70000000;  // thread-0-only history (tau_{i-1})

    for (int it = 0; it < 20; it++) {
        unsigned n = 0, s = 0;
        #pragma unroll
        for (int k = 0; k < KS; k++) {
            uint4 v = q128[tid + k * NT];
            int a0 = (int)(v.x & 0xFFFFu), a1 = (int)(v.x >> 16);
            int a2 = (int)(v.y & 0xFFFFu), a3 = (int)(v.y >> 16);
            int a4 = (int)(v.z & 0xFFFFu), a5 = (int)(v.z >> 16);
            int a6 = (int)(v.w & 0xFFFFu), a7 = (int)(v.w >> 16);
            if (a0 > qt) { n++; s += (unsigned)a0; }
            if (a1 > qt) { n++; s += (unsigned)a1; }
            if (a2 > qt) { n++; s += (unsigned)a2; }
            if (a3 > qt) { n++; s += (unsigned)a3; }
            if (a4 > qt) { n++; s += (unsigned)a4; }
            if (a5 > qt) { n++; s += (unsigned)a5; }
            if (a6 > qt) { n++; s += (unsigned)a6; }
            if (a7 > qt) { n++; s += (unsigned)a7; }
        }
        #pragma unroll
        for (int o = 16; o; o >>= 1) {
            n += __shfl_xor_sync(~0u, n, o);
            s += __shfl_xor_sync(~0u, s, o);
        }
        if (lane == 0) { sc->nred[warp] = n; sc->sred[warp] = s; }
        __syncthreads();

        if (warp == 0 && lane < 16) {
            unsigned N1 = sc->nred[lane];
            unsigned long long S1 = (unsigned long long)sc->sred[lane];
            #pragma unroll
            for (int o = 8; o; o >>= 1) {
                N1 += __shfl_xor_sync(0xFFFFu, N1, o);
                S1 += __shfl_xor_sync(0xFFFFu, S1, o);
            }
            if (lane == 0) {
                float s1 = (float)(((double)S1 + 0.5 * (double)N1) * (1.0 / 65536.0));
                float s0 = (float)Stot - s1;
                unsigned N0 = (unsigned)NPIX - N1;
                float c1 = s1 / (float)max(N1, 1u);
                float c0 = s0 / (float)max(N0, 1u);
                float t  = 0.5f * (c0 + c1);
                int qn = (int)floorf(t * 65536.0f - 0.5f);
                if (qn == qt) {                      // fixed point: all further steps no-op
                    sc->qt = qn; sc->done = 1;
                } else if (qn == prev) {             // 2-cycle {prev, qt}; pick by parity
                    int m = 19 - it;
                    sc->qt = ((m & 1) == 0) ? qn : qt;
                    sc->done = 1;
                } else {
                    prev = qt;
                    sc->qt = qn;
                }
            }
        }
        __syncthreads();
        qt = sc->qt;
        if (sc->done) break;
    }

    // ---------------- Phase 3a: border vote ----------------
    if (tid < 4) sc->border[tid] = 0;
    __syncthreads();
    #pragma unroll
    for (int i = tid; i < 1024; i += NT) {
        const int g = i >> 8;          // 0:row0 1:row255 2:col0 3:col255 (warp-uniform)
        const int j = i & 255;
        int qv;
        if      (g == 0) qv = (int)qs[j];
        else if (g == 1) qv = (int)qs[65280 + j];
        else if (g == 2) qv = (int)qs[j << 8];
        else             qv = (int)qs[(j << 8) + 255];
        unsigned c = (qv > qt) ? 1u : 0u;
        #pragma unroll
        for (int o = 16; o; o >>= 1) c += __shfl_xor_sync(~0u, c, o);
        if (lane == 0) atomicAdd(&sc->border[g], c);
    }
    __syncthreads();
    if (tid == 0) {
        int num = (sc->border[0] > 128u) + (sc->border[1] > 128u)
                + (sc->border[2] > 128u) + (sc->border[3] > 128u);
        sc->flip = (num >= 3) ? 1 : 0;
    }
    __syncthreads();
    const int flip = sc->flip;

    // ---------------- Phase 3b: loss vs sr_mask ----------------
    const float4* sp = (const float4*)(sr + (size_t)b * NPIX);
    float acc = 0.0f;
    #pragma unroll
    for (int k = 0; k < KG; k++) {
        int idx = tid + k * NT;
        unsigned long long v = q64[idx];
        float4 sv = sp[idx];
        int m0 = (((int)((unsigned)v & 0xFFFFu))         > qt) ^ flip;
        int m1 = (((int)(((unsigned)v >> 16) & 0xFFFFu)) > qt) ^ flip;
        int m2 = (((int)((unsigned)(v >> 32) & 0xFFFFu)) > qt) ^ flip;
        int m3 = (((int)((unsigned)(v >> 48)))           > qt) ^ flip;
        float d0 = sv.x - (float)m0;
        float d1 = sv.y - (float)m1;
        float d2 = sv.z - (float)m2;
        float d3 = sv.w - (float)m3;
        acc += d0 * d0 + d1 * d1 + d2 * d2 + d3 * d3;
    }
    #pragma unroll
    for (int o = 16; o; o >>= 1) acc += __shfl_xor_sync(~0u, acc, o);
    if (lane == 0) sc->facc[warp] = acc;
    __syncthreads();

    // ---------------- Phase 4: per-CTA partial + last-CTA finalize ----------------
    if (warp == 0) {
        float a = (lane < 16) ? sc->facc[lane] : 0.0f;
        #pragma unroll
        for (int o = 8; o; o >>= 1) a += __shfl_xor_sync(~0u, a, o);
        a = __shfl_sync(~0u, a, 0);
        if (lane == 0) g_partials[b] = (double)a;

        unsigned old = 0;
        if (lane == 0) {
            __threadfence();
            old = atomicAdd(&g_count, 1u);
        }
        old = __shfl_sync(~0u, old, 0);

        if (old == (unsigned)(B - 1)) {          // last CTA: finalize
            __threadfence();
            volatile double* vp = g_partials;
            double t = 0.0;
            for (int i = lane; i < B; i += 32) t += vp[i];
            #pragma unroll
            for (int o = 16; o; o >>= 1) t += __shfl_xor_sync(~0u, t, o);
            if (lane == 0) {
                out[0] = (float)(t / ((double)B * (double)NPIX));
                g_count = 0;                     // reset for next graph replay
            }
        }
    }
}

extern "C" void kernel_launch(void* const* d_in, const int* in_sizes, int n_in,
                              void* d_out, int out_size)
{
    const float* hr = (const float*)d_in[0];
    const float* sr = (const float*)d_in[1];
    int B = in_sizes[1] / NPIX;

    size_t smem = (size_t)NPIX * 2 + sizeof(Scratch);
    cudaFuncSetAttribute(mask_loss_main,
                         cudaFuncAttributeMaxDynamicSharedMemorySize, (int)smem);

    mask_loss_main<<<B, NT, smem>>>(hr, sr, (float*)d_out, B);
}